// round 4
// baseline (speedup 1.0000x reference)
#include <cuda_runtime.h>
#include <math_constants.h>
#include <cstdint>

// FilterDetection: score threshold + morphological opening (erode k=4 -> dilate k=4)
// cv2 semantics: erode offsets [-2,+1] (border +inf), dilate offsets [-1,+2]
// (eroded plane outside image = -inf).
//
// Register-pipeline kernel: each WARP owns a 128-col x 32-row strip.
// van Herk factorization: window-4 min = min(pair_{j-2}, pair_j), both axes.
// Horizontal via warp shuffles; vertical via 2-deep pairwise register rings.
// No shared memory, no __syncthreads. Pipeline prologue peeled.

#define CHUNK  128   // columns per warp (32 lanes x float4)
#define RSTRIP 32    // output rows per warp
#define WARPS  4     // warps per CTA (independent strips)

__device__ __forceinline__ float thr(float v) { return (v >= 0.5f) ? v : 0.0f; }

__global__ void score_thresh_kernel(const float* __restrict__ s,
                                    float* __restrict__ out, int n) {
    int i = blockIdx.x * blockDim.x + threadIdx.x;
    if (i < n) {
        float v = s[i];
        out[i] = (v >= 0.5f) ? v : 0.0f;
    }
}

__global__ __launch_bounds__(32 * WARPS, 9)
void open_kernel(const float* __restrict__ mask, float* __restrict__ out) {
    const int lane  = threadIdx.x;
    const int warp  = threadIdx.y;
    const int chunk = blockIdx.x;                       // 0..7
    const int c0    = chunk * CHUNK;
    const int r0    = (blockIdx.y * WARPS + warp) * RSTRIP;
    const float* img  = mask + (size_t)blockIdx.z * (1024u * 1024u);
    float*       oimg = out  + (size_t)blockIdx.z * (1024u * 1024u);
    const int col = c0 + lane * 4;

    const bool leftEdge  = (chunk == 0);
    const bool rightEdge = (chunk == 7);
    const float INF = CUDART_INF_F;

    // pipeline state (registers)
    float4 hprev;                 // h row (t-1)
    float4 pring[2];              // pairwise vertical mins of h
    float4 gprev;                 // g row (prev)
    float4 sring[2];              // pairwise vertical maxes of g
    float  hlprev, hr0prev, hr1prev;      // boundary h chains
    float  plr[2], pr0r[2], pr1r[2];      // boundary pairwise rings

    auto step = [&](int t, bool doP, bool doEV, bool doS, bool doOut)
        __attribute__((always_inline)) {
        const int ir  = r0 - 3 + t;
        const int par = t & 1;

        // ---- load input row (thresholded; OOB row -> +inf) ----
        float4 v;
        float xly, xlz, xlw, xrx, xry, xrz;
        xly = xlz = xlw = INF; xrx = xry = xrz = INF;
        if ((unsigned)ir < 1024u) {
            const float* rowp = img + (size_t)ir * 1024;
            float4 raw = *reinterpret_cast<const float4*>(rowp + col);
            v.x = thr(raw.x); v.y = thr(raw.y); v.z = thr(raw.z); v.w = thr(raw.w);
            if (lane == 0 && !leftEdge) {
                float4 b = *reinterpret_cast<const float4*>(rowp + c0 - 4);
                xly = thr(b.y); xlz = thr(b.z); xlw = thr(b.w);
            }
            if (lane == 31 && !rightEdge) {
                float4 b = *reinterpret_cast<const float4*>(rowp + c0 + CHUNK);
                xrx = thr(b.x); xry = thr(b.y); xrz = thr(b.z);
            }
        } else {
            v = make_float4(INF, INF, INF, INF);
        }

        // ---- horizontal erode: h_j = min(q_{j-2}, q_j), q_j = min(v_j, v_{j+1}) ----
        float vrx = __shfl_down_sync(0xffffffffu, v.x, 1);
        if (lane == 31) vrx = xrx;
        float4 q;
        q.x = fminf(v.x, v.y); q.y = fminf(v.y, v.z);
        q.z = fminf(v.z, v.w); q.w = fminf(v.w, vrx);
        float qpz = __shfl_up_sync(0xffffffffu, q.z, 1);   // q_{j-2} for j=0
        float qpw = __shfl_up_sync(0xffffffffu, q.w, 1);   // q_{j-2} for j=1
        if (lane == 0) { qpz = fminf(xlz, xlw); qpw = fminf(xlw, v.x); }
        float4 h;
        h.x = fminf(qpz, q.x); h.y = fminf(qpw, q.y);
        h.z = fminf(q.x, q.z); h.w = fminf(q.y, q.w);
        // boundary h (valid on lane0 / lane31 resp.)
        float hl  = fminf(fminf(xly, xlz), qpw);   // h @ col c0-1   (lane 0)
        float hr0 = fminf(q.z, fminf(xrx, xry));   // h @ col c0+128 (lane 31)
        float hr1 = fminf(q.w, fminf(xry, xrz));   // h @ col c0+129 (lane 31)

        if (doP) {
            // vertical erode pairwise: p_t = min(h_t, h_{t-1})
            float4 pn;
            pn.x = fminf(h.x, hprev.x); pn.y = fminf(h.y, hprev.y);
            pn.z = fminf(h.z, hprev.z); pn.w = fminf(h.w, hprev.w);
            float pln  = fminf(hl,  hlprev);
            float pr0n = fminf(hr0, hr0prev);
            float pr1n = fminf(hr1, hr1prev);

            if (doEV) {
                const int e = ir - 1;
                float4 ev; float evL, evR0, evR1;
                if ((unsigned)e < 1024u) {
                    float4 po = pring[par];        // p_{t-2}
                    ev.x = fminf(po.x, pn.x); ev.y = fminf(po.y, pn.y);
                    ev.z = fminf(po.z, pn.z); ev.w = fminf(po.w, pn.w);
                    evL  = fminf(plr[par],  pln);
                    evR0 = fminf(pr0r[par], pr0n);
                    evR1 = fminf(pr1r[par], pr1n);
                } else {
                    ev = make_float4(-INF, -INF, -INF, -INF);
                    evL = evR0 = evR1 = -INF;
                }

                // horizontal dilate: g_j = max(r_j, r_{j+2}), r_j = max(ev_{j-1}, ev_j)
                float evwu = __shfl_up_sync(0xffffffffu, ev.w, 1);
                if (lane == 0) evwu = leftEdge ? -INF : evL;
                float4 r;
                r.x = fmaxf(evwu, ev.x); r.y = fmaxf(ev.x, ev.y);
                r.z = fmaxf(ev.y, ev.z); r.w = fmaxf(ev.z, ev.w);
                float rnx = __shfl_down_sync(0xffffffffu, r.x, 1);
                float rny = __shfl_down_sync(0xffffffffu, r.y, 1);
                if (lane == 31) {
                    float a0 = rightEdge ? -INF : evR0;
                    float a1 = rightEdge ? -INF : evR1;
                    rnx = fmaxf(ev.w, a0);         // r @ col 128
                    rny = fmaxf(a0, a1);           // r @ col 129
                }
                float4 g;
                g.x = fmaxf(r.x, r.z); g.y = fmaxf(r.y, r.w);
                g.z = fmaxf(r.z, rnx); g.w = fmaxf(r.w, rny);

                if (doS) {
                    // vertical dilate pairwise: s_e = max(g_e, g_{e-1})
                    float4 sn;
                    sn.x = fmaxf(g.x, gprev.x); sn.y = fmaxf(g.y, gprev.y);
                    sn.z = fmaxf(g.z, gprev.z); sn.w = fmaxf(g.w, gprev.w);
                    if (doOut) {
                        float4 so = sring[par];    // s_{e-2}
                        float4 o4;
                        o4.x = fmaxf(so.x, sn.x); o4.y = fmaxf(so.y, sn.y);
                        o4.z = fmaxf(so.z, sn.z); o4.w = fmaxf(so.w, sn.w);
                        const int o = ir - 3;
                        *reinterpret_cast<float4*>(oimg + (size_t)o * 1024 + col) = o4;
                    }
                    sring[par] = sn;
                }
                gprev = g;
            }
            pring[par] = pn; plr[par] = pln; pr0r[par] = pr0n; pr1r[par] = pr1n;
        }
        hprev = h; hlprev = hl; hr0prev = hr0; hr1prev = hr1;
    };

    // pipeline prologue (peeled)
    step(0, false, false, false, false);
    step(1, true,  false, false, false);
    step(2, true,  false, false, false);
    step(3, true,  true,  false, false);
    step(4, true,  true,  true,  false);
    step(5, true,  true,  true,  false);
    // steady state: one output row per iteration
#pragma unroll 4
    for (int t = 6; t < RSTRIP + 6; ++t) {
        step(t, true, true, true, true);
    }
}

extern "C" void kernel_launch(void* const* d_in, const int* in_sizes, int n_in,
                              void* d_out, int out_size) {
    const float* score = (const float*)d_in[0];   // 32*1000
    const float* mask  = (const float*)d_in[1];   // 32*1024*1024
    float* out = (float*)d_out;

    const int n_score = in_sizes[0];              // 32000
    float* out_score = out;
    float* out_mask  = out + n_score;

    score_thresh_kernel<<<(n_score + 255) / 256, 256>>>(score, out_score, n_score);

    dim3 grid(1024 / CHUNK, 1024 / (RSTRIP * WARPS), 32);   // (8, 8, 32) = 2048 CTAs
    dim3 block(32, WARPS);
    open_kernel<<<grid, block>>>(mask, out_mask);
}